// round 12
// baseline (speedup 1.0000x reference)
#include <cuda_runtime.h>
#include <cuda_bf16.h>
#include <cuda_fp16.h>
#include <stdint.h>
#include <math.h>
#include <float.h>

#define DIMM   1024
#define NHEADS 16
#define SEQ    8192
#define NTOK   16384
#define BHTOT  32
#define NWIN   64
#define TBLROWS (SEQ + 256)
#define KDIM   1024

__device__ float g_qkv[(size_t)NTOK * 3072];
__device__ float g_v[(size_t)BHTOT * SEQ * 64];
__device__ float g_cos[(size_t)TBLROWS * 32];
__device__ float g_sin[(size_t)TBLROWS * 32];
__device__ __half g_a[(size_t)NTOK * KDIM];
__device__ __half g_b1[(size_t)3072 * KDIM];
__device__ __half g_b2[(size_t)1024 * KDIM];
__device__ __nv_bfloat16 g_qh[(size_t)BHTOT * SEQ * 64];
__device__ __nv_bfloat16 g_ql[(size_t)BHTOT * SEQ * 64];
__device__ __nv_bfloat16 g_kh[(size_t)BHTOT * SEQ * 64];
__device__ __nv_bfloat16 g_kl[(size_t)BHTOT * SEQ * 64];

__device__ __forceinline__ uint32_t smem_u32g(const void* p) {
    uint32_t a;
    asm("{ .reg .u64 t; cvta.to.shared.u64 t, %1; cvt.u32.u64 %0, t; }" : "=r"(a) : "l"(p));
    return a;
}
// bf16 mma (attention QK^T)
__device__ __forceinline__ void hmma16816(float c[4], uint32_t a0, uint32_t a1,
                                          uint32_t a2, uint32_t a3,
                                          uint32_t b0, uint32_t b1) {
    asm volatile("mma.sync.aligned.m16n8k16.row.col.f32.bf16.bf16.f32 "
        "{%0,%1,%2,%3}, {%4,%5,%6,%7}, {%8,%9}, {%0,%1,%2,%3};\n"
        : "+f"(c[0]), "+f"(c[1]), "+f"(c[2]), "+f"(c[3])
        : "r"(a0), "r"(a1), "r"(a2), "r"(a3), "r"(b0), "r"(b1));
}
// fp16 mma (gemms + attention PV)
__device__ __forceinline__ void hmma16816h(float c[4], uint32_t a0, uint32_t a1,
                                           uint32_t a2, uint32_t a3,
                                           uint32_t b0, uint32_t b1) {
    asm volatile("mma.sync.aligned.m16n8k16.row.col.f32.f16.f16.f32 "
        "{%0,%1,%2,%3}, {%4,%5,%6,%7}, {%8,%9}, {%0,%1,%2,%3};\n"
        : "+f"(c[0]), "+f"(c[1]), "+f"(c[2]), "+f"(c[3])
        : "r"(a0), "r"(a1), "r"(a2), "r"(a3), "r"(b0), "r"(b1));
}
#define LDMX4(r0,r1,r2,r3,addr) \
    asm volatile("ldmatrix.sync.aligned.m8n8.x4.shared.b16 {%0,%1,%2,%3}, [%4];" \
        : "=r"(r0),"=r"(r1),"=r"(r2),"=r"(r3) : "r"(addr))

__device__ __forceinline__ float fexp(float x) {
    x = fmaxf(x, -80.0f);
    float t = fmaf(x, 1.4426950408889634f, 12582912.0f);
    float i = t - 12582912.0f;
    float f = fmaf(x, 1.4426950408889634f, -i);
    float p =          1.3333558146e-3f;
    p = fmaf(p, f,     9.6181291057e-3f);
    p = fmaf(p, f,     5.5504108664e-2f);
    p = fmaf(p, f,     2.4022650695e-1f);
    p = fmaf(p, f,     6.9314718056e-1f);
    p = fmaf(p, f,     1.0f);
    return __int_as_float(__float_as_int(p) + (((int)i) << 23));
}
__device__ __forceinline__ uint32_t pack_h(float a, float b) {
    __half2 h = __floats2half2_rn(a, b);
    return *(uint32_t*)&h;
}

__global__ void rope_table_kernel() {
    int idx = blockIdx.x * 256 + threadIdx.x;
    if (idx >= TBLROWS * 32) return;
    int t = idx >> 5, d = idx & 31;
    float invf = expf(-(float)d * (9.210340371976184f / 32.0f));
    float s, c;
    sincosf((float)t * invf, &s, &c);
    g_cos[idx] = c; g_sin[idx] = s;
}

// ---------------- fp16 conversions ----------------
__global__ void __launch_bounds__(256) convert_a_h(
    const float* __restrict__ src, __half* __restrict__ dst)
{
    size_t i = ((size_t)blockIdx.x * 256 + threadIdx.x) * 4;
    float4 v = *(const float4*)(src + i);
    *(__half2*)(dst + i)     = __floats2half2_rn(v.x, v.y);
    *(__half2*)(dst + i + 2) = __floats2half2_rn(v.z, v.w);
}

__global__ void __launch_bounds__(1024) convert_b_h(
    const float* __restrict__ src, __half* __restrict__ dst, int N)
{
    __shared__ float t[32][33];
    int n0 = blockIdx.x * 32, k0 = blockIdx.y * 32;
    int tx = threadIdx.x, ty = threadIdx.y;
    t[ty][tx] = src[(size_t)(k0 + ty) * N + n0 + tx];
    __syncthreads();
    dst[(size_t)(n0 + ty) * KDIM + k0 + tx] = __float2half(t[tx][ty]);
}

// ------- fp16 HMMA GEMM: BM=256, BN=128, BK=64, 512 thr, fragment double-buffer
#define GEMM_NIT   (KDIM / 64)            // 16
#define STAGEU     ((256 + 128) * 36)     // rows of 144 B
#define NSTAGE     3
#define GEMM_SMEM  (NSTAGE * STAGEU * 4)  // 165888 B

__global__ void __launch_bounds__(512, 1) gemmh_kernel(
    const __half* __restrict__ A, const __half* __restrict__ Bm,
    float* __restrict__ C, int Ntot)
{
    extern __shared__ uint32_t smem[];
    int tid = threadIdx.x;
    int wid = tid >> 5, lane = tid & 31;
    int wm = wid >> 2, wn = wid & 3;
    int g = lane >> 2, tg = lane & 3;
    int lr = lane & 15, lh = lane >> 4;
    int brow = blockIdx.y, bcol = blockIdx.x;

    const __half* Ag = A + (size_t)(brow * 256) * KDIM;
    const __half* Bg = Bm + (size_t)(bcol * 128) * KDIM;
    uint32_t smb = smem_u32g(smem);

    int r0 = tid >> 3, c8 = tid & 7;

#define LOAD_STAGE(kc, stg) do { \
    uint32_t ab = smb + (stg) * STAGEU * 4; \
    uint32_t bb = ab + 256 * 144; \
    _Pragma("unroll") \
    for (int i = 0; i < 4; i++) { \
        int row = r0 + i * 64; \
        const __half* gA = Ag + (size_t)row * KDIM + (kc) * 64 + c8 * 8; \
        asm volatile("cp.async.cg.shared.global [%0], [%1], 16;" \
            :: "r"(ab + row * 144 + c8 * 16), "l"(gA)); \
    } \
    _Pragma("unroll") \
    for (int i = 0; i < 2; i++) { \
        int row = r0 + i * 64; \
        const __half* gB = Bg + (size_t)row * KDIM + (kc) * 64 + c8 * 8; \
        asm volatile("cp.async.cg.shared.global [%0], [%1], 16;" \
            :: "r"(bb + row * 144 + c8 * 16), "l"(gB)); \
    } \
} while (0)

// load one ks-step's fragments into buffer `buf`
#define LOAD_FRAGS(ks, buf) do { \
    _Pragma("unroll") \
    for (int mt = 0; mt < 4; mt++) { \
        uint32_t addr = as_u + (uint32_t)((wm * 64 + mt * 16 + lr) * 144 + (ks) * 32 + lh * 16); \
        LDMX4(af[buf][mt][0], af[buf][mt][1], af[buf][mt][2], af[buf][mt][3], addr); \
    } \
    _Pragma("unroll") \
    for (int bp = 0; bp < 2; bp++) { \
        uint32_t t0, t1, t2, t3; \
        uint32_t addr = bs_u + (uint32_t)((wn * 32 + bp * 16 + lr) * 144 + (ks) * 32 + lh * 16); \
        LDMX4(t0, t1, t2, t3, addr); \
        bt[buf][2*bp][0] = t0; bt[buf][2*bp][1] = t2; \
        bt[buf][2*bp+1][0] = t1; bt[buf][2*bp+1][1] = t3; \
    } \
} while (0)

    LOAD_STAGE(0, 0);
    asm volatile("cp.async.commit_group;" ::: "memory");
    LOAD_STAGE(1, 1);
    asm volatile("cp.async.commit_group;" ::: "memory");

    float acc[4][4][4];
    #pragma unroll
    for (int mt = 0; mt < 4; mt++)
        #pragma unroll
        for (int nt = 0; nt < 4; nt++)
            #pragma unroll
            for (int e = 0; e < 4; e++) acc[mt][nt][e] = 0.0f;

    uint32_t af[2][4][4], bt[2][4][2];

    for (int kc = 0; kc < GEMM_NIT; kc++) {
        int stg = kc % 3;
        asm volatile("cp.async.wait_group 1;" ::: "memory");
        __syncthreads();

        if (kc + 2 < GEMM_NIT) LOAD_STAGE(kc + 2, (kc + 2) % 3);
        asm volatile("cp.async.commit_group;" ::: "memory");

        uint32_t as_u = smb + stg * STAGEU * 4;
        uint32_t bs_u = as_u + 256 * 144;

        LOAD_FRAGS(0, 0);
        #pragma unroll
        for (int ks = 0; ks < 4; ks++) {
            int cur = ks & 1;
            if (ks < 3) LOAD_FRAGS(ks + 1, (ks + 1) & 1);
            #pragma unroll
            for (int mt = 0; mt < 4; mt++)
                #pragma unroll
                for (int nt = 0; nt < 4; nt++)
                    hmma16816h(acc[mt][nt],
                               af[cur][mt][0], af[cur][mt][1], af[cur][mt][2], af[cur][mt][3],
                               bt[cur][nt][0], bt[cur][nt][1]);
        }
    }

    #pragma unroll
    for (int mt = 0; mt < 4; mt++) {
        int row = brow * 256 + wm * 64 + mt * 16 + g;
        #pragma unroll
        for (int nt = 0; nt < 4; nt++) {
            int col = bcol * 128 + wn * 32 + nt * 8 + tg * 2;
            *(float2*)(C + (size_t)row * Ntot + col) = make_float2(acc[mt][nt][0], acc[mt][nt][1]);
            *(float2*)(C + (size_t)(row + 8) * Ntot + col) = make_float2(acc[mt][nt][2], acc[mt][nt][3]);
        }
    }
#undef LOAD_STAGE
#undef LOAD_FRAGS
}

// ---------------- norm + rope + split (bf16 hi/lo q,k; f32 v) ----------------
__global__ void __launch_bounds__(256) norm_rope_split_kernel(
    const float* __restrict__ qkv,
    const float* __restrict__ q_scale,
    const float* __restrict__ k_scale)
{
    int r = blockIdx.x * blockDim.y + threadIdx.y;
    int lane = threadIdx.x;
    int m = r >> 4, h = r & 15;
    int b = m >> 13, nn = m & (SEQ - 1);
    int bh = b * NHEADS + h;

    const float* row = qkv + (size_t)m * 3072 + h * 64;
    float q1 = row[lane],        q2 = row[lane + 32];
    float k1 = row[1024 + lane], k2 = row[1024 + lane + 32];
    float v1 = row[2048 + lane], v2 = row[2048 + lane + 32];

    float qs = q1 * q1 + q2 * q2, ks = k1 * k1 + k2 * k2;
    #pragma unroll
    for (int o = 16; o > 0; o >>= 1) {
        qs += __shfl_xor_sync(0xffffffffu, qs, o);
        ks += __shfl_xor_sync(0xffffffffu, ks, o);
    }
    float qinv = 8.0f / fmaxf(sqrtf(qs), 1e-12f);
    float kinv = 1.0f / fmaxf(sqrtf(ks), 1e-12f);
    q1 = q1 * qinv * q_scale[lane];  q2 = q2 * qinv * q_scale[lane + 32];
    k1 = k1 * kinv * k_scale[lane];  k2 = k2 * kinv * k_scale[lane + 32];

    int tq = nn + 128, tk = nn;
    float cq = g_cos[tq * 32 + lane], sq = g_sin[tq * 32 + lane];
    float ck = g_cos[tk * 32 + lane], sk = g_sin[tk * 32 + lane];
    float qo1 = q1 * cq - q2 * sq, qo2 = q2 * cq + q1 * sq;
    float ko1 = k1 * ck - k2 * sk, ko2 = k2 * ck + k1 * sk;

    size_t base = ((size_t)bh * SEQ + nn) * 64;
    __nv_bfloat16 t;
    t = __float2bfloat16(qo1); g_qh[base+lane]    = t; g_ql[base+lane]    = __float2bfloat16(qo1 - __bfloat162float(t));
    t = __float2bfloat16(qo2); g_qh[base+lane+32] = t; g_ql[base+lane+32] = __float2bfloat16(qo2 - __bfloat162float(t));
    t = __float2bfloat16(ko1); g_kh[base+lane]    = t; g_kl[base+lane]    = __float2bfloat16(ko1 - __bfloat162float(t));
    t = __float2bfloat16(ko2); g_kh[base+lane+32] = t; g_kl[base+lane+32] = __float2bfloat16(ko2 - __bfloat162float(t));
    g_v[base + lane] = v1; g_v[base + lane + 32] = v2;
}

// -------- windowed attention: QK^T split-bf16 (3 prod), PV fp16 (1 prod) -----
#define AQH 0u
#define AQL 18432u
#define AKH 36864u
#define AKL 55296u
#define AVH 73728u
#define ATTN_SMEM 91136

__global__ void __launch_bounds__(256) local_attn_kernel() {
    int w = blockIdx.x, bh = blockIdx.y;
    extern __shared__ __align__(16) unsigned char sm[];
    uint32_t smb = smem_u32g(sm);
    int tid = threadIdx.x, wid = tid >> 5, lane = tid & 31;
    int g = lane >> 2, tg = lane & 3, lr = lane & 15, lh = lane >> 4;

    size_t qoff = ((size_t)bh * SEQ + (size_t)w * 128) * 64;
    #pragma unroll
    for (int it = 0; it < 4; it++) {
        int c = tid + it * 256;
        int r = c >> 3, k16 = (c & 7) * 16;
        *(uint4*)(sm + AQH + r * 144 + k16) = *(const uint4*)((const char*)(g_qh + qoff + (size_t)r * 64) + k16);
        *(uint4*)(sm + AQL + r * 144 + k16) = *(const uint4*)((const char*)(g_ql + qoff + (size_t)r * 64) + k16);
    }

    float Oc[8][4];
    #pragma unroll
    for (int dt = 0; dt < 8; dt++)
        #pragma unroll
        for (int e = 0; e < 4; e++) Oc[dt][e] = 0.0f;
    float m0 = -1e30f, m1 = -1e30f, l0 = 0.0f, l1 = 0.0f;
    int r0 = wid * 16 + g, r1 = r0 + 8;
    uint32_t qrow = (uint32_t)((wid * 16 + lr) * 144 + lh * 16);

    for (int ch = 0; ch < 3; ch++) {
        int kw = w - 1 + ch;
        if (kw < 0 || kw >= NWIN) continue;
        size_t koff = ((size_t)bh * SEQ + (size_t)kw * 128) * 64;

        __syncthreads();
        #pragma unroll
        for (int it = 0; it < 4; it++) {
            int c = tid + it * 256;
            int r = c >> 3, k16 = (c & 7) * 16;
            *(uint4*)(sm + AKH + r * 144 + k16) = *(const uint4*)((const char*)(g_kh + koff + (size_t)r * 64) + k16);
            *(uint4*)(sm + AKL + r * 144 + k16) = *(const uint4*)((const char*)(g_kl + koff + (size_t)r * 64) + k16);
        }
        #pragma unroll
        for (int it = 0; it < 4; it++) {
            int t = tid + it * 256;
            int d4 = t & 15, j2 = t >> 4;
            float4 va = *(const float4*)(g_v + koff + (size_t)(2 * j2) * 64 + d4 * 4);
            float4 vb = *(const float4*)(g_v + koff + (size_t)(2 * j2 + 1) * 64 + d4 * 4);
            float a[4] = {va.x, va.y, va.z, va.w}, bb[4] = {vb.x, vb.y, vb.z, vb.w};
            #pragma unroll
            for (int dd = 0; dd < 4; dd++) {
                int d = d4 * 4 + dd;
                *(uint32_t*)(sm + AVH + d * 272 + j2 * 4) = pack_h(a[dd], bb[dd]);
            }
        }
        __syncthreads();

        float Sc[16][4];
        #pragma unroll
        for (int nt = 0; nt < 16; nt++)
            #pragma unroll
            for (int e = 0; e < 4; e++) Sc[nt][e] = 0.0f;

        #pragma unroll
        for (int kd = 0; kd < 4; kd++) {
            uint32_t ah[4], al[4];
            LDMX4(ah[0], ah[1], ah[2], ah[3], smb + AQH + qrow + kd * 32);
            LDMX4(al[0], al[1], al[2], al[3], smb + AQL + qrow + kd * 32);
            #pragma unroll
            for (int bp = 0; bp < 8; bp++) {
                uint32_t krow = (uint32_t)((bp * 16 + lr) * 144 + kd * 32 + lh * 16);
                uint32_t t0, t1, t2, t3, u0, u1, u2, u3;
                LDMX4(t0, t1, t2, t3, smb + AKH + krow);
                hmma16816(Sc[2*bp],   ah[0], ah[1], ah[2], ah[3], t0, t2);
                hmma16816(Sc[2*bp],   al[0], al[1], al[2], al[3], t0, t2);
                hmma16816(Sc[2*bp+1], ah[0], ah[1], ah[2], ah[3], t1, t3);
                hmma16816(Sc[2*bp+1], al[0], al[1], al[2], al[3], t1, t3);
                LDMX4(u0, u1, u2, u3, smb + AKL + krow);
                hmma16816(Sc[2*bp],   ah[0], ah[1], ah[2], ah[3], u0, u2);
                hmma16816(Sc[2*bp+1], ah[0], ah[1], ah[2], ah[3], u1, u3);
            }
        }

        if (ch == 0) {
            #pragma unroll
            for (int nt = 0; nt < 16; nt++) {
                int c0 = nt * 8 + tg * 2;
                if (c0 < r0)     Sc[nt][0] = -1e30f;
                if (c0 + 1 < r0) Sc[nt][1] = -1e30f;
                if (c0 < r1)     Sc[nt][2] = -1e30f;
                if (c0 + 1 < r1) Sc[nt][3] = -1e30f;
            }
        } else if (ch == 2) {
            #pragma unroll
            for (int nt = 0; nt < 16; nt++) {
                int c0 = nt * 8 + tg * 2;
                if (c0 > r0)     Sc[nt][0] = -1e30f;
                if (c0 + 1 > r0) Sc[nt][1] = -1e30f;
                if (c0 > r1)     Sc[nt][2] = -1e30f;
                if (c0 + 1 > r1) Sc[nt][3] = -1e30f;
            }
        }

        float rm0 = -1e30f, rm1 = -1e30f;
        #pragma unroll
        for (int nt = 0; nt < 16; nt++) {
            rm0 = fmaxf(rm0, fmaxf(Sc[nt][0], Sc[nt][1]));
            rm1 = fmaxf(rm1, fmaxf(Sc[nt][2], Sc[nt][3]));
        }
        rm0 = fmaxf(rm0, __shfl_xor_sync(0xffffffffu, rm0, 1));
        rm0 = fmaxf(rm0, __shfl_xor_sync(0xffffffffu, rm0, 2));
        rm1 = fmaxf(rm1, __shfl_xor_sync(0xffffffffu, rm1, 1));
        rm1 = fmaxf(rm1, __shfl_xor_sync(0xffffffffu, rm1, 2));
        float mn0 = fmaxf(m0, rm0), mn1 = fmaxf(m1, rm1);
        float a0 = fexp(m0 - mn0), a1 = fexp(m1 - mn1);
        float rs0 = 0.0f, rs1 = 0.0f;
        #pragma unroll
        for (int nt = 0; nt < 16; nt++) {
            Sc[nt][0] = fexp(Sc[nt][0] - mn0);
            Sc[nt][1] = fexp(Sc[nt][1] - mn0);
            Sc[nt][2] = fexp(Sc[nt][2] - mn1);
            Sc[nt][3] = fexp(Sc[nt][3] - mn1);
            rs0 += Sc[nt][0] + Sc[nt][1];
            rs1 += Sc[nt][2] + Sc[nt][3];
        }
        rs0 += __shfl_xor_sync(0xffffffffu, rs0, 1);
        rs0 += __shfl_xor_sync(0xffffffffu, rs0, 2);
        rs1 += __shfl_xor_sync(0xffffffffu, rs1, 1);
        rs1 += __shfl_xor_sync(0xffffffffu, rs1, 2);
        l0 = l0 * a0 + rs0; l1 = l1 * a1 + rs1;
        m0 = mn0; m1 = mn1;
        #pragma unroll
        for (int dt = 0; dt < 8; dt++) {
            Oc[dt][0] *= a0; Oc[dt][1] *= a0;
            Oc[dt][2] *= a1; Oc[dt][3] *= a1;
        }

        #pragma unroll
        for (int jt = 0; jt < 8; jt++) {
            uint32_t ph[4];
            float* s0 = Sc[2*jt];
            float* s1 = Sc[2*jt+1];
            ph[0] = pack_h(s0[0], s0[1]); ph[1] = pack_h(s0[2], s0[3]);
            ph[2] = pack_h(s1[0], s1[1]); ph[3] = pack_h(s1[2], s1[3]);
            #pragma unroll
            for (int dt = 0; dt < 4; dt++) {
                uint32_t vrow = (uint32_t)((dt * 16 + lr) * 272 + jt * 32 + lh * 16);
                uint32_t t0, t1, t2, t3;
                LDMX4(t0, t1, t2, t3, smb + AVH + vrow);
                hmma16816h(Oc[2*dt],   ph[0], ph[1], ph[2], ph[3], t0, t2);
                hmma16816h(Oc[2*dt+1], ph[0], ph[1], ph[2], ph[3], t1, t3);
            }
        }
    }

    float i0 = 1.0f / l0, i1 = 1.0f / l1;
    int b = bh >> 4, h = bh & 15;
    size_t mr0 = (size_t)(b * SEQ + w * 128 + r0) * KDIM;
    size_t mr1 = (size_t)(b * SEQ + w * 128 + r1) * KDIM;
    #pragma unroll
    for (int dt = 0; dt < 8; dt++) {
        int k = h * 64 + dt * 8 + tg * 2;
        *(__half2*)(g_a + mr0 + k) = __floats2half2_rn(Oc[dt][0] * i0, Oc[dt][1] * i0);
        *(__half2*)(g_a + mr1 + k) = __floats2half2_rn(Oc[dt][2] * i1, Oc[dt][3] * i1);
    }
}

// ---------------- launch ----------------
extern "C" void kernel_launch(void* const* d_in, const int* in_sizes, int n_in,
                              void* d_out, int out_size) {
    const float* x       = (const float*)d_in[0];
    const float* w_qkv   = (const float*)d_in[1];
    const float* w_out   = (const float*)d_in[2];
    const float* q_scale = (const float*)d_in[3];
    const float* k_scale = (const float*)d_in[4];
    float* out = (float*)d_out;

    void *p_qkv, *p_a, *p_b1, *p_b2;
    cudaGetSymbolAddress(&p_qkv, g_qkv);
    cudaGetSymbolAddress(&p_a, g_a);
    cudaGetSymbolAddress(&p_b1, g_b1);
    cudaGetSymbolAddress(&p_b2, g_b2);

    cudaFuncSetAttribute(local_attn_kernel,
                         cudaFuncAttributeMaxDynamicSharedMemorySize, ATTN_SMEM);
    cudaFuncSetAttribute(gemmh_kernel,
                         cudaFuncAttributeMaxDynamicSharedMemorySize, GEMM_SMEM);

    // gemm1 kept in the ncu-profiled slot (4th launch)
    rope_table_kernel<<<(TBLROWS * 32 + 255) / 256, 256>>>();
    convert_a_h<<<(NTOK * KDIM) / 1024, 256>>>(x, (__half*)p_a);
    convert_b_h<<<dim3(3072 / 32, 1024 / 32), dim3(32, 32)>>>(
        w_qkv, (__half*)p_b1, 3072);

    gemmh_kernel<<<dim3(3072 / 128, NTOK / 256), 512, GEMM_SMEM>>>(
        (const __half*)p_a, (const __half*)p_b1, (float*)p_qkv, 3072);

    convert_b_h<<<dim3(1024 / 32, 1024 / 32), dim3(32, 32)>>>(
        w_out, (__half*)p_b2, 1024);

    norm_rope_split_kernel<<<(NTOK * NHEADS) / 8, dim3(32, 8)>>>(
        (const float*)p_qkv, q_scale, k_scale);

    local_attn_kernel<<<dim3(NWIN, BHTOT), 256, ATTN_SMEM>>>();

    gemmh_kernel<<<dim3(1024 / 128, NTOK / 256), 512, GEMM_SMEM>>>(
        (const __half*)p_a, (const __half*)p_b2, out, 1024);
}

// round 14
// speedup vs baseline: 1.5414x; 1.5414x over previous
#include <cuda_runtime.h>
#include <cuda_bf16.h>
#include <cuda_fp16.h>
#include <stdint.h>
#include <math.h>
#include <float.h>

#define DIMM   1024
#define NHEADS 16
#define SEQ    8192
#define NTOK   16384
#define BHTOT  32
#define NWIN   64
#define TBLROWS (SEQ + 256)
#define KDIM   1024

__device__ float g_qkv[(size_t)NTOK * 3072];
__device__ __half g_vh[(size_t)BHTOT * SEQ * 64];
__device__ float g_cos[(size_t)TBLROWS * 32];
__device__ float g_sin[(size_t)TBLROWS * 32];
__device__ __half g_a[(size_t)NTOK * KDIM];
__device__ __half g_b1[(size_t)3072 * KDIM];
__device__ __half g_b2[(size_t)1024 * KDIM];
__device__ __nv_bfloat16 g_qh[(size_t)BHTOT * SEQ * 64];
__device__ __nv_bfloat16 g_ql[(size_t)BHTOT * SEQ * 64];
__device__ __nv_bfloat16 g_kh[(size_t)BHTOT * SEQ * 64];
__device__ __nv_bfloat16 g_kl[(size_t)BHTOT * SEQ * 64];

__device__ __forceinline__ uint32_t smem_u32g(const void* p) {
    uint32_t a;
    asm("{ .reg .u64 t; cvta.to.shared.u64 t, %1; cvt.u32.u64 %0, t; }" : "=r"(a) : "l"(p));
    return a;
}
// bf16 mma (attention QK^T)
__device__ __forceinline__ void hmma16816(float c[4], uint32_t a0, uint32_t a1,
                                          uint32_t a2, uint32_t a3,
                                          uint32_t b0, uint32_t b1) {
    asm volatile("mma.sync.aligned.m16n8k16.row.col.f32.bf16.bf16.f32 "
        "{%0,%1,%2,%3}, {%4,%5,%6,%7}, {%8,%9}, {%0,%1,%2,%3};\n"
        : "+f"(c[0]), "+f"(c[1]), "+f"(c[2]), "+f"(c[3])
        : "r"(a0), "r"(a1), "r"(a2), "r"(a3), "r"(b0), "r"(b1));
}
// fp16 mma (gemms + attention PV)
__device__ __forceinline__ void hmma16816h(float c[4], uint32_t a0, uint32_t a1,
                                           uint32_t a2, uint32_t a3,
                                           uint32_t b0, uint32_t b1) {
    asm volatile("mma.sync.aligned.m16n8k16.row.col.f32.f16.f16.f32 "
        "{%0,%1,%2,%3}, {%4,%5,%6,%7}, {%8,%9}, {%0,%1,%2,%3};\n"
        : "+f"(c[0]), "+f"(c[1]), "+f"(c[2]), "+f"(c[3])
        : "r"(a0), "r"(a1), "r"(a2), "r"(a3), "r"(b0), "r"(b1));
}
#define LDMX4(r0,r1,r2,r3,addr) \
    asm volatile("ldmatrix.sync.aligned.m8n8.x4.shared.b16 {%0,%1,%2,%3}, [%4];" \
        : "=r"(r0),"=r"(r1),"=r"(r2),"=r"(r3) : "r"(addr))

__device__ __forceinline__ float fexp(float x) {
    x = fmaxf(x, -80.0f);
    float t = fmaf(x, 1.4426950408889634f, 12582912.0f);
    float i = t - 12582912.0f;
    float f = fmaf(x, 1.4426950408889634f, -i);
    float p =          1.3333558146e-3f;
    p = fmaf(p, f,     9.6181291057e-3f);
    p = fmaf(p, f,     5.5504108664e-2f);
    p = fmaf(p, f,     2.4022650695e-1f);
    p = fmaf(p, f,     6.9314718056e-1f);
    p = fmaf(p, f,     1.0f);
    return __int_as_float(__float_as_int(p) + (((int)i) << 23));
}
__device__ __forceinline__ uint32_t pack_h(float a, float b) {
    __half2 h = __floats2half2_rn(a, b);
    return *(uint32_t*)&h;
}

__global__ void rope_table_kernel() {
    int idx = blockIdx.x * 256 + threadIdx.x;
    if (idx >= TBLROWS * 32) return;
    int t = idx >> 5, d = idx & 31;
    float invf = expf(-(float)d * (9.210340371976184f / 32.0f));
    float s, c;
    sincosf((float)t * invf, &s, &c);
    g_cos[idx] = c; g_sin[idx] = s;
}

// ---------------- fp16 conversions ----------------
__global__ void __launch_bounds__(256) convert_a_h(
    const float* __restrict__ src, __half* __restrict__ dst)
{
    size_t i = ((size_t)blockIdx.x * 256 + threadIdx.x) * 4;
    float4 v = *(const float4*)(src + i);
    *(__half2*)(dst + i)     = __floats2half2_rn(v.x, v.y);
    *(__half2*)(dst + i + 2) = __floats2half2_rn(v.z, v.w);
}

__global__ void __launch_bounds__(1024) convert_b_h(
    const float* __restrict__ src, __half* __restrict__ dst, int N)
{
    __shared__ float t[32][33];
    int n0 = blockIdx.x * 32, k0 = blockIdx.y * 32;
    int tx = threadIdx.x, ty = threadIdx.y;
    t[ty][tx] = src[(size_t)(k0 + ty) * N + n0 + tx];
    __syncthreads();
    dst[(size_t)(n0 + ty) * KDIM + k0 + tx] = __float2half(t[tx][ty]);
}

// ------- fp16 HMMA GEMM: BM=256, BN=128, BK=64, 512 thr, 16 warps (R10 proven)
#define GEMM_NIT   (KDIM / 64)            // 16
#define STAGEU     ((256 + 128) * 36)     // rows of 144 B
#define NSTAGE     3
#define GEMM_SMEM  (NSTAGE * STAGEU * 4)  // 165888 B

__global__ void __launch_bounds__(512, 1) gemmh_kernel(
    const __half* __restrict__ A, const __half* __restrict__ Bm,
    float* __restrict__ C, int Ntot)
{
    extern __shared__ uint32_t smem[];
    int tid = threadIdx.x;
    int wid = tid >> 5, lane = tid & 31;
    int wm = wid >> 2, wn = wid & 3;
    int g = lane >> 2, tg = lane & 3;
    int lr = lane & 15, lh = lane >> 4;
    int brow = blockIdx.y, bcol = blockIdx.x;

    const __half* Ag = A + (size_t)(brow * 256) * KDIM;
    const __half* Bg = Bm + (size_t)(bcol * 128) * KDIM;
    uint32_t smb = smem_u32g(smem);

    int r0 = tid >> 3, c8 = tid & 7;

#define LOAD_STAGE(kc, stg) do { \
    uint32_t ab = smb + (stg) * STAGEU * 4; \
    uint32_t bb = ab + 256 * 144; \
    _Pragma("unroll") \
    for (int i = 0; i < 4; i++) { \
        int row = r0 + i * 64; \
        const __half* gA = Ag + (size_t)row * KDIM + (kc) * 64 + c8 * 8; \
        asm volatile("cp.async.cg.shared.global [%0], [%1], 16;" \
            :: "r"(ab + row * 144 + c8 * 16), "l"(gA)); \
    } \
    _Pragma("unroll") \
    for (int i = 0; i < 2; i++) { \
        int row = r0 + i * 64; \
        const __half* gB = Bg + (size_t)row * KDIM + (kc) * 64 + c8 * 8; \
        asm volatile("cp.async.cg.shared.global [%0], [%1], 16;" \
            :: "r"(bb + row * 144 + c8 * 16), "l"(gB)); \
    } \
} while (0)

    LOAD_STAGE(0, 0);
    asm volatile("cp.async.commit_group;" ::: "memory");
    LOAD_STAGE(1, 1);
    asm volatile("cp.async.commit_group;" ::: "memory");

    float acc[4][4][4];
    #pragma unroll
    for (int mt = 0; mt < 4; mt++)
        #pragma unroll
        for (int nt = 0; nt < 4; nt++)
            #pragma unroll
            for (int e = 0; e < 4; e++) acc[mt][nt][e] = 0.0f;

    for (int kc = 0; kc < GEMM_NIT; kc++) {
        int stg = kc % 3;
        asm volatile("cp.async.wait_group 1;" ::: "memory");
        __syncthreads();

        if (kc + 2 < GEMM_NIT) LOAD_STAGE(kc + 2, (kc + 2) % 3);
        asm volatile("cp.async.commit_group;" ::: "memory");

        uint32_t as_u = smb + stg * STAGEU * 4;
        uint32_t bs_u = as_u + 256 * 144;

        #pragma unroll
        for (int ks = 0; ks < 4; ks++) {
            uint32_t af[4][4], bt[4][2];
            #pragma unroll
            for (int mt = 0; mt < 4; mt++) {
                uint32_t addr = as_u + (uint32_t)((wm * 64 + mt * 16 + lr) * 144 + ks * 32 + lh * 16);
                LDMX4(af[mt][0], af[mt][1], af[mt][2], af[mt][3], addr);
            }
            #pragma unroll
            for (int bp = 0; bp < 2; bp++) {
                uint32_t t0, t1, t2, t3;
                uint32_t addr = bs_u + (uint32_t)((wn * 32 + bp * 16 + lr) * 144 + ks * 32 + lh * 16);
                LDMX4(t0, t1, t2, t3, addr);
                bt[2*bp][0] = t0; bt[2*bp][1] = t2;
                bt[2*bp+1][0] = t1; bt[2*bp+1][1] = t3;
            }
            #pragma unroll
            for (int mt = 0; mt < 4; mt++)
                #pragma unroll
                for (int nt = 0; nt < 4; nt++)
                    hmma16816h(acc[mt][nt], af[mt][0], af[mt][1], af[mt][2], af[mt][3],
                               bt[nt][0], bt[nt][1]);
        }
    }

    #pragma unroll
    for (int mt = 0; mt < 4; mt++) {
        int row = brow * 256 + wm * 64 + mt * 16 + g;
        #pragma unroll
        for (int nt = 0; nt < 4; nt++) {
            int col = bcol * 128 + wn * 32 + nt * 8 + tg * 2;
            *(float2*)(C + (size_t)row * Ntot + col) = make_float2(acc[mt][nt][0], acc[mt][nt][1]);
            *(float2*)(C + (size_t)(row + 8) * Ntot + col) = make_float2(acc[mt][nt][2], acc[mt][nt][3]);
        }
    }
#undef LOAD_STAGE
}

// ---------------- norm + rope + split (bf16 hi/lo q,k; fp16 v) ----------------
__global__ void __launch_bounds__(256) norm_rope_split_kernel(
    const float* __restrict__ qkv,
    const float* __restrict__ q_scale,
    const float* __restrict__ k_scale)
{
    int r = blockIdx.x * blockDim.y + threadIdx.y;
    int lane = threadIdx.x;
    int m = r >> 4, h = r & 15;
    int b = m >> 13, nn = m & (SEQ - 1);
    int bh = b * NHEADS + h;

    const float* row = qkv + (size_t)m * 3072 + h * 64;
    float q1 = row[lane],        q2 = row[lane + 32];
    float k1 = row[1024 + lane], k2 = row[1024 + lane + 32];
    float v1 = row[2048 + lane], v2 = row[2048 + lane + 32];

    float qs = q1 * q1 + q2 * q2, ks = k1 * k1 + k2 * k2;
    #pragma unroll
    for (int o = 16; o > 0; o >>= 1) {
        qs += __shfl_xor_sync(0xffffffffu, qs, o);
        ks += __shfl_xor_sync(0xffffffffu, ks, o);
    }
    float qinv = 8.0f / fmaxf(sqrtf(qs), 1e-12f);
    float kinv = 1.0f / fmaxf(sqrtf(ks), 1e-12f);
    q1 = q1 * qinv * q_scale[lane];  q2 = q2 * qinv * q_scale[lane + 32];
    k1 = k1 * kinv * k_scale[lane];  k2 = k2 * kinv * k_scale[lane + 32];

    int tq = nn + 128, tk = nn;
    float cq = g_cos[tq * 32 + lane], sq = g_sin[tq * 32 + lane];
    float ck = g_cos[tk * 32 + lane], sk = g_sin[tk * 32 + lane];
    float qo1 = q1 * cq - q2 * sq, qo2 = q2 * cq + q1 * sq;
    float ko1 = k1 * ck - k2 * sk, ko2 = k2 * ck + k1 * sk;

    size_t base = ((size_t)bh * SEQ + nn) * 64;
    __nv_bfloat16 t;
    t = __float2bfloat16(qo1); g_qh[base+lane]    = t; g_ql[base+lane]    = __float2bfloat16(qo1 - __bfloat162float(t));
    t = __float2bfloat16(qo2); g_qh[base+lane+32] = t; g_ql[base+lane+32] = __float2bfloat16(qo2 - __bfloat162float(t));
    t = __float2bfloat16(ko1); g_kh[base+lane]    = t; g_kl[base+lane]    = __float2bfloat16(ko1 - __bfloat162float(t));
    t = __float2bfloat16(ko2); g_kh[base+lane+32] = t; g_kl[base+lane+32] = __float2bfloat16(ko2 - __bfloat162float(t));
    g_vh[base + lane]      = __float2half(v1);
    g_vh[base + lane + 32] = __float2half(v2);
}

// -------- windowed attention: QK^T split-bf16 (3 prod), PV fp16 (1 prod) -----
#define AQH 0u
#define AQL 18432u
#define AKH 36864u
#define AKL 55296u
#define AVH 73728u
#define ATTN_SMEM 91136

__global__ void __launch_bounds__(256) local_attn_kernel() {
    int w = blockIdx.x, bh = blockIdx.y;
    extern __shared__ __align__(16) unsigned char sm[];
    uint32_t smb = smem_u32g(sm);
    int tid = threadIdx.x, wid = tid >> 5, lane = tid & 31;
    int g = lane >> 2, tg = lane & 3, lr = lane & 15, lh = lane >> 4;

    size_t qoff = ((size_t)bh * SEQ + (size_t)w * 128) * 64;
    #pragma unroll
    for (int it = 0; it < 4; it++) {
        int c = tid + it * 256;
        int r = c >> 3, k16 = (c & 7) * 16;
        *(uint4*)(sm + AQH + r * 144 + k16) = *(const uint4*)((const char*)(g_qh + qoff + (size_t)r * 64) + k16);
        *(uint4*)(sm + AQL + r * 144 + k16) = *(const uint4*)((const char*)(g_ql + qoff + (size_t)r * 64) + k16);
    }

    float Oc[8][4];
    #pragma unroll
    for (int dt = 0; dt < 8; dt++)
        #pragma unroll
        for (int e = 0; e < 4; e++) Oc[dt][e] = 0.0f;
    float m0 = -1e30f, m1 = -1e30f, l0 = 0.0f, l1 = 0.0f;
    int r0 = wid * 16 + g, r1 = r0 + 8;
    uint32_t qrow = (uint32_t)((wid * 16 + lr) * 144 + lh * 16);

    for (int ch = 0; ch < 3; ch++) {
        int kw = w - 1 + ch;
        if (kw < 0 || kw >= NWIN) continue;
        size_t koff = ((size_t)bh * SEQ + (size_t)kw * 128) * 64;

        __syncthreads();
        #pragma unroll
        for (int it = 0; it < 4; it++) {
            int c = tid + it * 256;
            int r = c >> 3, k16 = (c & 7) * 16;
            *(uint4*)(sm + AKH + r * 144 + k16) = *(const uint4*)((const char*)(g_kh + koff + (size_t)r * 64) + k16);
            *(uint4*)(sm + AKL + r * 144 + k16) = *(const uint4*)((const char*)(g_kl + koff + (size_t)r * 64) + k16);
        }
        // V: fp16 source; transpose to [d][j] half2 pairs via byte_perm
        #pragma unroll
        for (int it = 0; it < 4; it++) {
            int t = tid + it * 256;
            int d4 = t & 15, j2 = t >> 4;
            uint2 ua = *(const uint2*)(g_vh + koff + (size_t)(2 * j2) * 64 + d4 * 4);
            uint2 ub = *(const uint2*)(g_vh + koff + (size_t)(2 * j2 + 1) * 64 + d4 * 4);
            int d = d4 * 4;
            *(uint32_t*)(sm + AVH + (d + 0) * 272 + j2 * 4) = __byte_perm(ua.x, ub.x, 0x5410);
            *(uint32_t*)(sm + AVH + (d + 1) * 272 + j2 * 4) = __byte_perm(ua.x, ub.x, 0x7632);
            *(uint32_t*)(sm + AVH + (d + 2) * 272 + j2 * 4) = __byte_perm(ua.y, ub.y, 0x5410);
            *(uint32_t*)(sm + AVH + (d + 3) * 272 + j2 * 4) = __byte_perm(ua.y, ub.y, 0x7632);
        }
        __syncthreads();

        float Sc[16][4];
        #pragma unroll
        for (int nt = 0; nt < 16; nt++)
            #pragma unroll
            for (int e = 0; e < 4; e++) Sc[nt][e] = 0.0f;

        #pragma unroll
        for (int kd = 0; kd < 4; kd++) {
            uint32_t ah[4], al[4];
            LDMX4(ah[0], ah[1], ah[2], ah[3], smb + AQH + qrow + kd * 32);
            LDMX4(al[0], al[1], al[2], al[3], smb + AQL + qrow + kd * 32);
            #pragma unroll
            for (int bp = 0; bp < 8; bp++) {
                uint32_t krow = (uint32_t)((bp * 16 + lr) * 144 + kd * 32 + lh * 16);
                uint32_t t0, t1, t2, t3, u0, u1, u2, u3;
                LDMX4(t0, t1, t2, t3, smb + AKH + krow);
                hmma16816(Sc[2*bp],   ah[0], ah[1], ah[2], ah[3], t0, t2);
                hmma16816(Sc[2*bp],   al[0], al[1], al[2], al[3], t0, t2);
                hmma16816(Sc[2*bp+1], ah[0], ah[1], ah[2], ah[3], t1, t3);
                hmma16816(Sc[2*bp+1], al[0], al[1], al[2], al[3], t1, t3);
                LDMX4(u0, u1, u2, u3, smb + AKL + krow);
                hmma16816(Sc[2*bp],   ah[0], ah[1], ah[2], ah[3], u0, u2);
                hmma16816(Sc[2*bp+1], ah[0], ah[1], ah[2], ah[3], u1, u3);
            }
        }

        if (ch == 0) {
            #pragma unroll
            for (int nt = 0; nt < 16; nt++) {
                int c0 = nt * 8 + tg * 2;
                if (c0 < r0)     Sc[nt][0] = -1e30f;
                if (c0 + 1 < r0) Sc[nt][1] = -1e30f;
                if (c0 < r1)     Sc[nt][2] = -1e30f;
                if (c0 + 1 < r1) Sc[nt][3] = -1e30f;
            }
        } else if (ch == 2) {
            #pragma unroll
            for (int nt = 0; nt < 16; nt++) {
                int c0 = nt * 8 + tg * 2;
                if (c0 > r0)     Sc[nt][0] = -1e30f;
                if (c0 + 1 > r0) Sc[nt][1] = -1e30f;
                if (c0 > r1)     Sc[nt][2] = -1e30f;
                if (c0 + 1 > r1) Sc[nt][3] = -1e30f;
            }
        }

        float rm0 = -1e30f, rm1 = -1e30f;
        #pragma unroll
        for (int nt = 0; nt < 16; nt++) {
            rm0 = fmaxf(rm0, fmaxf(Sc[nt][0], Sc[nt][1]));
            rm1 = fmaxf(rm1, fmaxf(Sc[nt][2], Sc[nt][3]));
        }
        rm0 = fmaxf(rm0, __shfl_xor_sync(0xffffffffu, rm0, 1));
        rm0 = fmaxf(rm0, __shfl_xor_sync(0xffffffffu, rm0, 2));
        rm1 = fmaxf(rm1, __shfl_xor_sync(0xffffffffu, rm1, 1));
        rm1 = fmaxf(rm1, __shfl_xor_sync(0xffffffffu, rm1, 2));
        float mn0 = fmaxf(m0, rm0), mn1 = fmaxf(m1, rm1);
        float a0 = fexp(m0 - mn0), a1 = fexp(m1 - mn1);
        float rs0 = 0.0f, rs1 = 0.0f;
        #pragma unroll
        for (int nt = 0; nt < 16; nt++) {
            Sc[nt][0] = fexp(Sc[nt][0] - mn0);
            Sc[nt][1] = fexp(Sc[nt][1] - mn0);
            Sc[nt][2] = fexp(Sc[nt][2] - mn1);
            Sc[nt][3] = fexp(Sc[nt][3] - mn1);
            rs0 += Sc[nt][0] + Sc[nt][1];
            rs1 += Sc[nt][2] + Sc[nt][3];
        }
        rs0 += __shfl_xor_sync(0xffffffffu, rs0, 1);
        rs0 += __shfl_xor_sync(0xffffffffu, rs0, 2);
        rs1 += __shfl_xor_sync(0xffffffffu, rs1, 1);
        rs1 += __shfl_xor_sync(0xffffffffu, rs1, 2);
        l0 = l0 * a0 + rs0; l1 = l1 * a1 + rs1;
        m0 = mn0; m1 = mn1;
        #pragma unroll
        for (int dt = 0; dt < 8; dt++) {
            Oc[dt][0] *= a0; Oc[dt][1] *= a0;
            Oc[dt][2] *= a1; Oc[dt][3] *= a1;
        }

        #pragma unroll
        for (int jt = 0; jt < 8; jt++) {
            uint32_t ph[4];
            float* s0 = Sc[2*jt];
            float* s1 = Sc[2*jt+1];
            ph[0] = pack_h(s0[0], s0[1]); ph[1] = pack_h(s0[2], s0[3]);
            ph[2] = pack_h(s1[0], s1[1]); ph[3] = pack_h(s1[2], s1[3]);
            #pragma unroll
            for (int dt = 0; dt < 4; dt++) {
                uint32_t vrow = (uint32_t)((dt * 16 + lr) * 272 + jt * 32 + lh * 16);
                uint32_t t0, t1, t2, t3;
                LDMX4(t0, t1, t2, t3, smb + AVH + vrow);
                hmma16816h(Oc[2*dt],   ph[0], ph[1], ph[2], ph[3], t0, t2);
                hmma16816h(Oc[2*dt+1], ph[0], ph[1], ph[2], ph[3], t1, t3);
            }
        }
    }

    float i0 = 1.0f / l0, i1 = 1.0f / l1;
    int b = bh >> 4, h = bh & 15;
    size_t mr0 = (size_t)(b * SEQ + w * 128 + r0) * KDIM;
    size_t mr1 = (size_t)(b * SEQ + w * 128 + r1) * KDIM;
    #pragma unroll
    for (int dt = 0; dt < 8; dt++) {
        int k = h * 64 + dt * 8 + tg * 2;
        *(__half2*)(g_a + mr0 + k) = __floats2half2_rn(Oc[dt][0] * i0, Oc[dt][1] * i0);
        *(__half2*)(g_a + mr1 + k) = __floats2half2_rn(Oc[dt][2] * i1, Oc[dt][3] * i1);
    }
}

// ---------------- launch ----------------
extern "C" void kernel_launch(void* const* d_in, const int* in_sizes, int n_in,
                              void* d_out, int out_size) {
    const float* x       = (const float*)d_in[0];
    const float* w_qkv   = (const float*)d_in[1];
    const float* w_out   = (const float*)d_in[2];
    const float* q_scale = (const float*)d_in[3];
    const float* k_scale = (const float*)d_in[4];
    float* out = (float*)d_out;

    void *p_qkv, *p_a, *p_b1, *p_b2;
    cudaGetSymbolAddress(&p_qkv, g_qkv);
    cudaGetSymbolAddress(&p_a, g_a);
    cudaGetSymbolAddress(&p_b1, g_b1);
    cudaGetSymbolAddress(&p_b2, g_b2);

    cudaFuncSetAttribute(local_attn_kernel,
                         cudaFuncAttributeMaxDynamicSharedMemorySize, ATTN_SMEM);
    cudaFuncSetAttribute(gemmh_kernel,
                         cudaFuncAttributeMaxDynamicSharedMemorySize, GEMM_SMEM);

    // gemm1 kept in the ncu-profiled slot (4th launch)
    rope_table_kernel<<<(TBLROWS * 32 + 255) / 256, 256>>>();
    convert_a_h<<<(NTOK * KDIM) / 1024, 256>>>(x, (__half*)p_a);
    convert_b_h<<<dim3(3072 / 32, 1024 / 32), dim3(32, 32)>>>(
        w_qkv, (__half*)p_b1, 3072);

    gemmh_kernel<<<dim3(3072 / 128, NTOK / 256), 512, GEMM_SMEM>>>(
        (const __half*)p_a, (const __half*)p_b1, (float*)p_qkv, 3072);

    convert_b_h<<<dim3(1024 / 32, 1024 / 32), dim3(32, 32)>>>(
        w_out, (__half*)p_b2, 1024);

    norm_rope_split_kernel<<<(NTOK * NHEADS) / 8, dim3(32, 8)>>>(
        (const float*)p_qkv, q_scale, k_scale);

    local_attn_kernel<<<dim3(NWIN, BHTOT), 256, ATTN_SMEM>>>();

    gemmh_kernel<<<dim3(1024 / 128, NTOK / 256), 512, GEMM_SMEM>>>(
        (const __half*)p_a, (const __half*)p_b2, out, 1024);
}

// round 15
// speedup vs baseline: 1.7399x; 1.1288x over previous
#include <cuda_runtime.h>
#include <cuda_bf16.h>
#include <cuda_fp16.h>
#include <stdint.h>
#include <math.h>
#include <float.h>

#define DIMM   1024
#define NHEADS 16
#define SEQ    8192
#define NTOK   16384
#define BHTOT  32
#define NWIN   64
#define TBLROWS (SEQ + 256)
#define KDIM   1024

__device__ float g_qkv[(size_t)NTOK * 3072];
__device__ __half g_vh[(size_t)BHTOT * SEQ * 64];
__device__ float g_cos[(size_t)TBLROWS * 32];
__device__ float g_sin[(size_t)TBLROWS * 32];
__device__ __half g_a[(size_t)NTOK * KDIM];
__device__ __half g_b1[(size_t)3072 * KDIM];
__device__ __half g_b2[(size_t)1024 * KDIM];
__device__ __half g_q16[(size_t)BHTOT * SEQ * 64];
__device__ __half g_k16[(size_t)BHTOT * SEQ * 64];

__device__ __forceinline__ uint32_t smem_u32g(const void* p) {
    uint32_t a;
    asm("{ .reg .u64 t; cvta.to.shared.u64 t, %1; cvt.u32.u64 %0, t; }" : "=r"(a) : "l"(p));
    return a;
}
// fp16 mma (gemms + attention)
__device__ __forceinline__ void hmma16816h(float c[4], uint32_t a0, uint32_t a1,
                                           uint32_t a2, uint32_t a3,
                                           uint32_t b0, uint32_t b1) {
    asm volatile("mma.sync.aligned.m16n8k16.row.col.f32.f16.f16.f32 "
        "{%0,%1,%2,%3}, {%4,%5,%6,%7}, {%8,%9}, {%0,%1,%2,%3};\n"
        : "+f"(c[0]), "+f"(c[1]), "+f"(c[2]), "+f"(c[3])
        : "r"(a0), "r"(a1), "r"(a2), "r"(a3), "r"(b0), "r"(b1));
}
#define LDMX4(r0,r1,r2,r3,addr) \
    asm volatile("ldmatrix.sync.aligned.m8n8.x4.shared.b16 {%0,%1,%2,%3}, [%4];" \
        : "=r"(r0),"=r"(r1),"=r"(r2),"=r"(r3) : "r"(addr))

__device__ __forceinline__ float fexp(float x) {
    x = fmaxf(x, -80.0f);
    float t = fmaf(x, 1.4426950408889634f, 12582912.0f);
    float i = t - 12582912.0f;
    float f = fmaf(x, 1.4426950408889634f, -i);
    float p =          1.3333558146e-3f;
    p = fmaf(p, f,     9.6181291057e-3f);
    p = fmaf(p, f,     5.5504108664e-2f);
    p = fmaf(p, f,     2.4022650695e-1f);
    p = fmaf(p, f,     6.9314718056e-1f);
    p = fmaf(p, f,     1.0f);
    return __int_as_float(__float_as_int(p) + (((int)i) << 23));
}
__device__ __forceinline__ uint32_t pack_h(float a, float b) {
    __half2 h = __floats2half2_rn(a, b);
    return *(uint32_t*)&h;
}

__global__ void rope_table_kernel() {
    int idx = blockIdx.x * 256 + threadIdx.x;
    if (idx >= TBLROWS * 32) return;
    int t = idx >> 5, d = idx & 31;
    float invf = expf(-(float)d * (9.210340371976184f / 32.0f));
    float s, c;
    sincosf((float)t * invf, &s, &c);
    g_cos[idx] = c; g_sin[idx] = s;
}

// ---------------- fp16 conversions ----------------
__global__ void __launch_bounds__(256) convert_a_h(
    const float* __restrict__ src, __half* __restrict__ dst)
{
    size_t i = ((size_t)blockIdx.x * 256 + threadIdx.x) * 4;
    float4 v = *(const float4*)(src + i);
    *(__half2*)(dst + i)     = __floats2half2_rn(v.x, v.y);
    *(__half2*)(dst + i + 2) = __floats2half2_rn(v.z, v.w);
}

__global__ void __launch_bounds__(1024) convert_b_h(
    const float* __restrict__ src, __half* __restrict__ dst, int N)
{
    __shared__ float t[32][33];
    int n0 = blockIdx.x * 32, k0 = blockIdx.y * 32;
    int tx = threadIdx.x, ty = threadIdx.y;
    t[ty][tx] = src[(size_t)(k0 + ty) * N + n0 + tx];
    __syncthreads();
    dst[(size_t)(n0 + ty) * KDIM + k0 + tx] = __float2half(t[tx][ty]);
}

// ------- fp16 HMMA GEMM: BM=256, BN=128, BK=64, 512 thr, 16 warps (frozen)
#define GEMM_NIT   (KDIM / 64)            // 16
#define STAGEU     ((256 + 128) * 36)     // rows of 144 B
#define NSTAGE     3
#define GEMM_SMEM  (NSTAGE * STAGEU * 4)  // 165888 B

__global__ void __launch_bounds__(512, 1) gemmh_kernel(
    const __half* __restrict__ A, const __half* __restrict__ Bm,
    float* __restrict__ C, int Ntot)
{
    extern __shared__ uint32_t smem[];
    int tid = threadIdx.x;
    int wid = tid >> 5, lane = tid & 31;
    int wm = wid >> 2, wn = wid & 3;
    int g = lane >> 2, tg = lane & 3;
    int lr = lane & 15, lh = lane >> 4;
    int brow = blockIdx.y, bcol = blockIdx.x;

    const __half* Ag = A + (size_t)(brow * 256) * KDIM;
    const __half* Bg = Bm + (size_t)(bcol * 128) * KDIM;
    uint32_t smb = smem_u32g(smem);

    int r0 = tid >> 3, c8 = tid & 7;

#define LOAD_STAGE(kc, stg) do { \
    uint32_t ab = smb + (stg) * STAGEU * 4; \
    uint32_t bb = ab + 256 * 144; \
    _Pragma("unroll") \
    for (int i = 0; i < 4; i++) { \
        int row = r0 + i * 64; \
        const __half* gA = Ag + (size_t)row * KDIM + (kc) * 64 + c8 * 8; \
        asm volatile("cp.async.cg.shared.global [%0], [%1], 16;" \
            :: "r"(ab + row * 144 + c8 * 16), "l"(gA)); \
    } \
    _Pragma("unroll") \
    for (int i = 0; i < 2; i++) { \
        int row = r0 + i * 64; \
        const __half* gB = Bg + (size_t)row * KDIM + (kc) * 64 + c8 * 8; \
        asm volatile("cp.async.cg.shared.global [%0], [%1], 16;" \
            :: "r"(bb + row * 144 + c8 * 16), "l"(gB)); \
    } \
} while (0)

    LOAD_STAGE(0, 0);
    asm volatile("cp.async.commit_group;" ::: "memory");
    LOAD_STAGE(1, 1);
    asm volatile("cp.async.commit_group;" ::: "memory");

    float acc[4][4][4];
    #pragma unroll
    for (int mt = 0; mt < 4; mt++)
        #pragma unroll
        for (int nt = 0; nt < 4; nt++)
            #pragma unroll
            for (int e = 0; e < 4; e++) acc[mt][nt][e] = 0.0f;

    for (int kc = 0; kc < GEMM_NIT; kc++) {
        int stg = kc % 3;
        asm volatile("cp.async.wait_group 1;" ::: "memory");
        __syncthreads();

        if (kc + 2 < GEMM_NIT) LOAD_STAGE(kc + 2, (kc + 2) % 3);
        asm volatile("cp.async.commit_group;" ::: "memory");

        uint32_t as_u = smb + stg * STAGEU * 4;
        uint32_t bs_u = as_u + 256 * 144;

        #pragma unroll
        for (int ks = 0; ks < 4; ks++) {
            uint32_t af[4][4], bt[4][2];
            #pragma unroll
            for (int mt = 0; mt < 4; mt++) {
                uint32_t addr = as_u + (uint32_t)((wm * 64 + mt * 16 + lr) * 144 + ks * 32 + lh * 16);
                LDMX4(af[mt][0], af[mt][1], af[mt][2], af[mt][3], addr);
            }
            #pragma unroll
            for (int bp = 0; bp < 2; bp++) {
                uint32_t t0, t1, t2, t3;
                uint32_t addr = bs_u + (uint32_t)((wn * 32 + bp * 16 + lr) * 144 + ks * 32 + lh * 16);
                LDMX4(t0, t1, t2, t3, addr);
                bt[2*bp][0] = t0; bt[2*bp][1] = t2;
                bt[2*bp+1][0] = t1; bt[2*bp+1][1] = t3;
            }
            #pragma unroll
            for (int mt = 0; mt < 4; mt++)
                #pragma unroll
                for (int nt = 0; nt < 4; nt++)
                    hmma16816h(acc[mt][nt], af[mt][0], af[mt][1], af[mt][2], af[mt][3],
                               bt[nt][0], bt[nt][1]);
        }
    }

    #pragma unroll
    for (int mt = 0; mt < 4; mt++) {
        int row = brow * 256 + wm * 64 + mt * 16 + g;
        #pragma unroll
        for (int nt = 0; nt < 4; nt++) {
            int col = bcol * 128 + wn * 32 + nt * 8 + tg * 2;
            *(float2*)(C + (size_t)row * Ntot + col) = make_float2(acc[mt][nt][0], acc[mt][nt][1]);
            *(float2*)(C + (size_t)(row + 8) * Ntot + col) = make_float2(acc[mt][nt][2], acc[mt][nt][3]);
        }
    }
#undef LOAD_STAGE
}

// ---------------- norm + rope + split (fp16 q,k,v) ----------------
__global__ void __launch_bounds__(256) norm_rope_split_kernel(
    const float* __restrict__ qkv,
    const float* __restrict__ q_scale,
    const float* __restrict__ k_scale)
{
    int r = blockIdx.x * blockDim.y + threadIdx.y;
    int lane = threadIdx.x;
    int m = r >> 4, h = r & 15;
    int b = m >> 13, nn = m & (SEQ - 1);
    int bh = b * NHEADS + h;

    const float* row = qkv + (size_t)m * 3072 + h * 64;
    float q1 = row[lane],        q2 = row[lane + 32];
    float k1 = row[1024 + lane], k2 = row[1024 + lane + 32];
    float v1 = row[2048 + lane], v2 = row[2048 + lane + 32];

    float qs = q1 * q1 + q2 * q2, ks = k1 * k1 + k2 * k2;
    #pragma unroll
    for (int o = 16; o > 0; o >>= 1) {
        qs += __shfl_xor_sync(0xffffffffu, qs, o);
        ks += __shfl_xor_sync(0xffffffffu, ks, o);
    }
    float qinv = 8.0f / fmaxf(sqrtf(qs), 1e-12f);
    float kinv = 1.0f / fmaxf(sqrtf(ks), 1e-12f);
    q1 = q1 * qinv * q_scale[lane];  q2 = q2 * qinv * q_scale[lane + 32];
    k1 = k1 * kinv * k_scale[lane];  k2 = k2 * kinv * k_scale[lane + 32];

    int tq = nn + 128, tk = nn;
    float cq = g_cos[tq * 32 + lane], sq = g_sin[tq * 32 + lane];
    float ck = g_cos[tk * 32 + lane], sk = g_sin[tk * 32 + lane];
    float qo1 = q1 * cq - q2 * sq, qo2 = q2 * cq + q1 * sq;
    float ko1 = k1 * ck - k2 * sk, ko2 = k2 * ck + k1 * sk;

    size_t base = ((size_t)bh * SEQ + nn) * 64;
    g_q16[base + lane]      = __float2half(qo1);
    g_q16[base + lane + 32] = __float2half(qo2);
    g_k16[base + lane]      = __float2half(ko1);
    g_k16[base + lane + 32] = __float2half(ko2);
    g_vh[base + lane]       = __float2half(v1);
    g_vh[base + lane + 32]  = __float2half(v2);
}

// -------- windowed attention: all-fp16 HMMA flash (QK^T 1 prod, PV 1 prod) ---
#define AQ 0u
#define AK 18432u
#define AV 36864u
#define ATTN_SMEM 54272

__global__ void __launch_bounds__(256, 2) local_attn_kernel() {
    int w = blockIdx.x, bh = blockIdx.y;
    extern __shared__ __align__(16) unsigned char sm[];
    uint32_t smb = smem_u32g(sm);
    int tid = threadIdx.x, wid = tid >> 5, lane = tid & 31;
    int g = lane >> 2, tg = lane & 3, lr = lane & 15, lh = lane >> 4;

    size_t qoff = ((size_t)bh * SEQ + (size_t)w * 128) * 64;
    #pragma unroll
    for (int it = 0; it < 4; it++) {
        int c = tid + it * 256;
        int r = c >> 3, k16 = (c & 7) * 16;
        *(uint4*)(sm + AQ + r * 144 + k16) = *(const uint4*)((const char*)(g_q16 + qoff + (size_t)r * 64) + k16);
    }

    float Oc[8][4];
    #pragma unroll
    for (int dt = 0; dt < 8; dt++)
        #pragma unroll
        for (int e = 0; e < 4; e++) Oc[dt][e] = 0.0f;
    float m0 = -1e30f, m1 = -1e30f, l0 = 0.0f, l1 = 0.0f;
    int r0 = wid * 16 + g, r1 = r0 + 8;
    uint32_t qrow = (uint32_t)((wid * 16 + lr) * 144 + lh * 16);

    for (int ch = 0; ch < 3; ch++) {
        int kw = w - 1 + ch;
        if (kw < 0 || kw >= NWIN) continue;
        size_t koff = ((size_t)bh * SEQ + (size_t)kw * 128) * 64;

        __syncthreads();
        #pragma unroll
        for (int it = 0; it < 4; it++) {
            int c = tid + it * 256;
            int r = c >> 3, k16 = (c & 7) * 16;
            *(uint4*)(sm + AK + r * 144 + k16) = *(const uint4*)((const char*)(g_k16 + koff + (size_t)r * 64) + k16);
        }
        // V: fp16 source; transpose to [d][j] half2 pairs via byte_perm
        #pragma unroll
        for (int it = 0; it < 4; it++) {
            int t = tid + it * 256;
            int d4 = t & 15, j2 = t >> 4;
            uint2 ua = *(const uint2*)(g_vh + koff + (size_t)(2 * j2) * 64 + d4 * 4);
            uint2 ub = *(const uint2*)(g_vh + koff + (size_t)(2 * j2 + 1) * 64 + d4 * 4);
            int d = d4 * 4;
            *(uint32_t*)(sm + AV + (d + 0) * 272 + j2 * 4) = __byte_perm(ua.x, ub.x, 0x5410);
            *(uint32_t*)(sm + AV + (d + 1) * 272 + j2 * 4) = __byte_perm(ua.x, ub.x, 0x7632);
            *(uint32_t*)(sm + AV + (d + 2) * 272 + j2 * 4) = __byte_perm(ua.y, ub.y, 0x5410);
            *(uint32_t*)(sm + AV + (d + 3) * 272 + j2 * 4) = __byte_perm(ua.y, ub.y, 0x7632);
        }
        __syncthreads();

        float Sc[16][4];
        #pragma unroll
        for (int nt = 0; nt < 16; nt++)
            #pragma unroll
            for (int e = 0; e < 4; e++) Sc[nt][e] = 0.0f;

        #pragma unroll
        for (int kd = 0; kd < 4; kd++) {
            uint32_t ah[4];
            LDMX4(ah[0], ah[1], ah[2], ah[3], smb + AQ + qrow + kd * 32);
            #pragma unroll
            for (int bp = 0; bp < 8; bp++) {
                uint32_t krow = (uint32_t)((bp * 16 + lr) * 144 + kd * 32 + lh * 16);
                uint32_t t0, t1, t2, t3;
                LDMX4(t0, t1, t2, t3, smb + AK + krow);
                hmma16816h(Sc[2*bp],   ah[0], ah[1], ah[2], ah[3], t0, t2);
                hmma16816h(Sc[2*bp+1], ah[0], ah[1], ah[2], ah[3], t1, t3);
            }
        }

        if (ch == 0) {
            #pragma unroll
            for (int nt = 0; nt < 16; nt++) {
                int c0 = nt * 8 + tg * 2;
                if (c0 < r0)     Sc[nt][0] = -1e30f;
                if (c0 + 1 < r0) Sc[nt][1] = -1e30f;
                if (c0 < r1)     Sc[nt][2] = -1e30f;
                if (c0 + 1 < r1) Sc[nt][3] = -1e30f;
            }
        } else if (ch == 2) {
            #pragma unroll
            for (int nt = 0; nt < 16; nt++) {
                int c0 = nt * 8 + tg * 2;
                if (c0 > r0)     Sc[nt][0] = -1e30f;
                if (c0 + 1 > r0) Sc[nt][1] = -1e30f;
                if (c0 > r1)     Sc[nt][2] = -1e30f;
                if (c0 + 1 > r1) Sc[nt][3] = -1e30f;
            }
        }

        float rm0 = -1e30f, rm1 = -1e30f;
        #pragma unroll
        for (int nt = 0; nt < 16; nt++) {
            rm0 = fmaxf(rm0, fmaxf(Sc[nt][0], Sc[nt][1]));
            rm1 = fmaxf(rm1, fmaxf(Sc[nt][2], Sc[nt][3]));
        }
        rm0 = fmaxf(rm0, __shfl_xor_sync(0xffffffffu, rm0, 1));
        rm0 = fmaxf(rm0, __shfl_xor_sync(0xffffffffu, rm0, 2));
        rm1 = fmaxf(rm1, __shfl_xor_sync(0xffffffffu, rm1, 1));
        rm1 = fmaxf(rm1, __shfl_xor_sync(0xffffffffu, rm1, 2));
        float mn0 = fmaxf(m0, rm0), mn1 = fmaxf(m1, rm1);
        float a0 = fexp(m0 - mn0), a1 = fexp(m1 - mn1);
        float rs0 = 0.0f, rs1 = 0.0f;
        #pragma unroll
        for (int nt = 0; nt < 16; nt++) {
            Sc[nt][0] = fexp(Sc[nt][0] - mn0);
            Sc[nt][1] = fexp(Sc[nt][1] - mn0);
            Sc[nt][2] = fexp(Sc[nt][2] - mn1);
            Sc[nt][3] = fexp(Sc[nt][3] - mn1);
            rs0 += Sc[nt][0] + Sc[nt][1];
            rs1 += Sc[nt][2] + Sc[nt][3];
        }
        rs0 += __shfl_xor_sync(0xffffffffu, rs0, 1);
        rs0 += __shfl_xor_sync(0xffffffffu, rs0, 2);
        rs1 += __shfl_xor_sync(0xffffffffu, rs1, 1);
        rs1 += __shfl_xor_sync(0xffffffffu, rs1, 2);
        l0 = l0 * a0 + rs0; l1 = l1 * a1 + rs1;
        m0 = mn0; m1 = mn1;
        #pragma unroll
        for (int dt = 0; dt < 8; dt++) {
            Oc[dt][0] *= a0; Oc[dt][1] *= a0;
            Oc[dt][2] *= a1; Oc[dt][3] *= a1;
        }

        #pragma unroll
        for (int jt = 0; jt < 8; jt++) {
            uint32_t ph[4];
            float* s0 = Sc[2*jt];
            float* s1 = Sc[2*jt+1];
            ph[0] = pack_h(s0[0], s0[1]); ph[1] = pack_h(s0[2], s0[3]);
            ph[2] = pack_h(s1[0], s1[1]); ph[3] = pack_h(s1[2], s1[3]);
            #pragma unroll
            for (int dt = 0; dt < 4; dt++) {
                uint32_t vrow = (uint32_t)((dt * 16 + lr) * 272 + jt * 32 + lh * 16);
                uint32_t t0, t1, t2, t3;
                LDMX4(t0, t1, t2, t3, smb + AV + vrow);
                hmma16816h(Oc[2*dt],   ph[0], ph[1], ph[2], ph[3], t0, t2);
                hmma16816h(Oc[2*dt+1], ph[0], ph[1], ph[2], ph[3], t1, t3);
            }
        }
    }

    float i0 = 1.0f / l0, i1 = 1.0f / l1;
    int b = bh >> 4, h = bh & 15;
    size_t mr0 = (size_t)(b * SEQ + w * 128 + r0) * KDIM;
    size_t mr1 = (size_t)(b * SEQ + w * 128 + r1) * KDIM;
    #pragma unroll
    for (int dt = 0; dt < 8; dt++) {
        int k = h * 64 + dt * 8 + tg * 2;
        *(__half2*)(g_a + mr0 + k) = __floats2half2_rn(Oc[dt][0] * i0, Oc[dt][1] * i0);
        *(__half2*)(g_a + mr1 + k) = __floats2half2_rn(Oc[dt][2] * i1, Oc[dt][3] * i1);
    }
}

// ---------------- launch ----------------
extern "C" void kernel_launch(void* const* d_in, const int* in_sizes, int n_in,
                              void* d_out, int out_size) {
    const float* x       = (const float*)d_in[0];
    const float* w_qkv   = (const float*)d_in[1];
    const float* w_out   = (const float*)d_in[2];
    const float* q_scale = (const float*)d_in[3];
    const float* k_scale = (const float*)d_in[4];
    float* out = (float*)d_out;

    void *p_qkv, *p_a, *p_b1, *p_b2;
    cudaGetSymbolAddress(&p_qkv, g_qkv);
    cudaGetSymbolAddress(&p_a, g_a);
    cudaGetSymbolAddress(&p_b1, g_b1);
    cudaGetSymbolAddress(&p_b2, g_b2);

    cudaFuncSetAttribute(local_attn_kernel,
                         cudaFuncAttributeMaxDynamicSharedMemorySize, ATTN_SMEM);
    cudaFuncSetAttribute(gemmh_kernel,
                         cudaFuncAttributeMaxDynamicSharedMemorySize, GEMM_SMEM);

    // gemm1 kept in the ncu-profiled slot (4th launch)
    rope_table_kernel<<<(TBLROWS * 32 + 255) / 256, 256>>>();
    convert_a_h<<<(NTOK * KDIM) / 1024, 256>>>(x, (__half*)p_a);
    convert_b_h<<<dim3(3072 / 32, 1024 / 32), dim3(32, 32)>>>(
        w_qkv, (__half*)p_b1, 3072);

    gemmh_kernel<<<dim3(3072 / 128, NTOK / 256), 512, GEMM_SMEM>>>(
        (const __half*)p_a, (const __half*)p_b1, (float*)p_qkv, 3072);

    convert_b_h<<<dim3(1024 / 32, 1024 / 32), dim3(32, 32)>>>(
        w_out, (__half*)p_b2, 1024);

    norm_rope_split_kernel<<<(NTOK * NHEADS) / 8, dim3(32, 8)>>>(
        (const float*)p_qkv, q_scale, k_scale);

    local_attn_kernel<<<dim3(NWIN, BHTOT), 256, ATTN_SMEM>>>();

    gemmh_kernel<<<dim3(1024 / 128, NTOK / 256), 512, GEMM_SMEM>>>(
        (const __half*)p_a, (const __half*)p_b2, out, 1024);
}

// round 17
// speedup vs baseline: 1.7404x; 1.0003x over previous
#include <cuda_runtime.h>
#include <cuda_bf16.h>
#include <cuda_fp16.h>
#include <stdint.h>
#include <math.h>
#include <float.h>

#define DIMM   1024
#define NHEADS 16
#define SEQ    8192
#define NTOK   16384
#define BHTOT  32
#define NWIN   64
#define TBLROWS (SEQ + 256)
#define KDIM   1024

__device__ __half g_qkv16[(size_t)NTOK * 3072];
__device__ __half g_vh[(size_t)BHTOT * SEQ * 64];
__device__ float g_cos[(size_t)TBLROWS * 32];
__device__ float g_sin[(size_t)TBLROWS * 32];
__device__ __half g_a[(size_t)NTOK * KDIM];
__device__ __half g_b1[(size_t)3072 * KDIM];
__device__ __half g_b2[(size_t)1024 * KDIM];
__device__ __half g_q16[(size_t)BHTOT * SEQ * 64];
__device__ __half g_k16[(size_t)BHTOT * SEQ * 64];

__device__ __forceinline__ uint32_t smem_u32g(const void* p) {
    uint32_t a;
    asm("{ .reg .u64 t; cvta.to.shared.u64 t, %1; cvt.u32.u64 %0, t; }" : "=r"(a) : "l"(p));
    return a;
}
__device__ __forceinline__ void hmma16816h(float c[4], uint32_t a0, uint32_t a1,
                                           uint32_t a2, uint32_t a3,
                                           uint32_t b0, uint32_t b1) {
    asm volatile("mma.sync.aligned.m16n8k16.row.col.f32.f16.f16.f32 "
        "{%0,%1,%2,%3}, {%4,%5,%6,%7}, {%8,%9}, {%0,%1,%2,%3};\n"
        : "+f"(c[0]), "+f"(c[1]), "+f"(c[2]), "+f"(c[3])
        : "r"(a0), "r"(a1), "r"(a2), "r"(a3), "r"(b0), "r"(b1));
}
#define LDMX4(r0,r1,r2,r3,addr) \
    asm volatile("ldmatrix.sync.aligned.m8n8.x4.shared.b16 {%0,%1,%2,%3}, [%4];" \
        : "=r"(r0),"=r"(r1),"=r"(r2),"=r"(r3) : "r"(addr))

__device__ __forceinline__ float fexp(float x) {
    x = fmaxf(x, -80.0f);
    float t = fmaf(x, 1.4426950408889634f, 12582912.0f);
    float i = t - 12582912.0f;
    float f = fmaf(x, 1.4426950408889634f, -i);
    float p =          1.3333558146e-3f;
    p = fmaf(p, f,     9.6181291057e-3f);
    p = fmaf(p, f,     5.5504108664e-2f);
    p = fmaf(p, f,     2.4022650695e-1f);
    p = fmaf(p, f,     6.9314718056e-1f);
    p = fmaf(p, f,     1.0f);
    return __int_as_float(__float_as_int(p) + (((int)i) << 23));
}
__device__ __forceinline__ uint32_t pack_h(float a, float b) {
    __half2 h = __floats2half2_rn(a, b);
    return *(uint32_t*)&h;
}

__global__ void rope_table_kernel() {
    int idx = blockIdx.x * 256 + threadIdx.x;
    if (idx >= TBLROWS * 32) return;
    int t = idx >> 5, d = idx & 31;
    float invf = expf(-(float)d * (9.210340371976184f / 32.0f));
    float s, c;
    sincosf((float)t * invf, &s, &c);
    g_cos[idx] = c; g_sin[idx] = s;
}

// ---------------- fp16 conversions ----------------
__global__ void __launch_bounds__(256) convert_a_h(
    const float* __restrict__ src, __half* __restrict__ dst)
{
    size_t i = ((size_t)blockIdx.x * 256 + threadIdx.x) * 4;
    float4 v = *(const float4*)(src + i);
    *(__half2*)(dst + i)     = __floats2half2_rn(v.x, v.y);
    *(__half2*)(dst + i + 2) = __floats2half2_rn(v.z, v.w);
}

__global__ void __launch_bounds__(1024) convert_b_h(
    const float* __restrict__ src, __half* __restrict__ dst, int N)
{
    __shared__ float t[32][33];
    int n0 = blockIdx.x * 32, k0 = blockIdx.y * 32;
    int tx = threadIdx.x, ty = threadIdx.y;
    t[ty][tx] = src[(size_t)(k0 + ty) * N + n0 + tx];
    __syncthreads();
    dst[(size_t)(n0 + ty) * KDIM + k0 + tx] = __float2half(t[tx][ty]);
}

// ------- fp16 HMMA GEMM: BM=256, BN=128, BK=64, 512 thr (mainloop frozen) ----
#define GEMM_NIT   (KDIM / 64)            // 16
#define STAGEU     ((256 + 128) * 36)     // rows of 144 B
#define NSTAGE     3
#define GEMM_SMEM  (NSTAGE * STAGEU * 4)  // 165888 B

__global__ void __launch_bounds__(512, 1) gemmh_kernel(
    const __half* __restrict__ A, const __half* __restrict__ Bm,
    float* __restrict__ C, int Ntot, int halfOut)
{
    extern __shared__ uint32_t smem[];
    int tid = threadIdx.x;
    int wid = tid >> 5, lane = tid & 31;
    int wm = wid >> 2, wn = wid & 3;
    int g = lane >> 2, tg = lane & 3;
    int lr = lane & 15, lh = lane >> 4;
    int brow = blockIdx.y, bcol = blockIdx.x;

    const __half* Ag = A + (size_t)(brow * 256) * KDIM;
    const __half* Bg = Bm + (size_t)(bcol * 128) * KDIM;
    uint32_t smb = smem_u32g(smem);

    int r0 = tid >> 3, c8 = tid & 7;

#define LOAD_STAGE(kc, stg) do { \
    uint32_t ab = smb + (stg) * STAGEU * 4; \
    uint32_t bb = ab + 256 * 144; \
    _Pragma("unroll") \
    for (int i = 0; i < 4; i++) { \
        int row = r0 + i * 64; \
        const __half* gA = Ag + (size_t)row * KDIM + (kc) * 64 + c8 * 8; \
        asm volatile("cp.async.cg.shared.global [%0], [%1], 16;" \
            :: "r"(ab + row * 144 + c8 * 16), "l"(gA)); \
    } \
    _Pragma("unroll") \
    for (int i = 0; i < 2; i++) { \
        int row = r0 + i * 64; \
        const __half* gB = Bg + (size_t)row * KDIM + (kc) * 64 + c8 * 8; \
        asm volatile("cp.async.cg.shared.global [%0], [%1], 16;" \
            :: "r"(bb + row * 144 + c8 * 16), "l"(gB)); \
    } \
} while (0)

    LOAD_STAGE(0, 0);
    asm volatile("cp.async.commit_group;" ::: "memory");
    LOAD_STAGE(1, 1);
    asm volatile("cp.async.commit_group;" ::: "memory");

    float acc[4][4][4];
    #pragma unroll
    for (int mt = 0; mt < 4; mt++)
        #pragma unroll
        for (int nt = 0; nt < 4; nt++)
            #pragma unroll
            for (int e = 0; e < 4; e++) acc[mt][nt][e] = 0.0f;

    for (int kc = 0; kc < GEMM_NIT; kc++) {
        int stg = kc % 3;
        asm volatile("cp.async.wait_group 1;" ::: "memory");
        __syncthreads();

        if (kc + 2 < GEMM_NIT) LOAD_STAGE(kc + 2, (kc + 2) % 3);
        asm volatile("cp.async.commit_group;" ::: "memory");

        uint32_t as_u = smb + stg * STAGEU * 4;
        uint32_t bs_u = as_u + 256 * 144;

        #pragma unroll
        for (int ks = 0; ks < 4; ks++) {
            uint32_t af[4][4], bt[4][2];
            #pragma unroll
            for (int mt = 0; mt < 4; mt++) {
                uint32_t addr = as_u + (uint32_t)((wm * 64 + mt * 16 + lr) * 144 + ks * 32 + lh * 16);
                LDMX4(af[mt][0], af[mt][1], af[mt][2], af[mt][3], addr);
            }
            #pragma unroll
            for (int bp = 0; bp < 2; bp++) {
                uint32_t t0, t1, t2, t3;
                uint32_t addr = bs_u + (uint32_t)((wn * 32 + bp * 16 + lr) * 144 + ks * 32 + lh * 16);
                LDMX4(t0, t1, t2, t3, addr);
                bt[2*bp][0] = t0; bt[2*bp][1] = t2;
                bt[2*bp+1][0] = t1; bt[2*bp+1][1] = t3;
            }
            #pragma unroll
            for (int mt = 0; mt < 4; mt++)
                #pragma unroll
                for (int nt = 0; nt < 4; nt++)
                    hmma16816h(acc[mt][nt], af[mt][0], af[mt][1], af[mt][2], af[mt][3],
                               bt[nt][0], bt[nt][1]);
        }
    }

    if (halfOut) {
        __half* Ch = (__half*)C;
        #pragma unroll
        for (int mt = 0; mt < 4; mt++) {
            int row = brow * 256 + wm * 64 + mt * 16 + g;
            #pragma unroll
            for (int nt = 0; nt < 4; nt++) {
                int col = bcol * 128 + wn * 32 + nt * 8 + tg * 2;
                *(uint32_t*)(Ch + (size_t)row * Ntot + col)       = pack_h(acc[mt][nt][0], acc[mt][nt][1]);
                *(uint32_t*)(Ch + (size_t)(row + 8) * Ntot + col) = pack_h(acc[mt][nt][2], acc[mt][nt][3]);
            }
        }
    } else {
        #pragma unroll
        for (int mt = 0; mt < 4; mt++) {
            int row = brow * 256 + wm * 64 + mt * 16 + g;
            #pragma unroll
            for (int nt = 0; nt < 4; nt++) {
                int col = bcol * 128 + wn * 32 + nt * 8 + tg * 2;
                *(float2*)(C + (size_t)row * Ntot + col) = make_float2(acc[mt][nt][0], acc[mt][nt][1]);
                *(float2*)(C + (size_t)(row + 8) * Ntot + col) = make_float2(acc[mt][nt][2], acc[mt][nt][3]);
            }
        }
    }
#undef LOAD_STAGE
}

// ---------------- norm + rope + split (fp16 in, fp16 q,k,v out) --------------
__global__ void __launch_bounds__(256) norm_rope_split_kernel(
    const __half* __restrict__ qkv,
    const float* __restrict__ q_scale,
    const float* __restrict__ k_scale)
{
    int r = blockIdx.x * blockDim.y + threadIdx.y;
    int lane = threadIdx.x;
    int m = r >> 4, h = r & 15;
    int b = m >> 13, nn = m & (SEQ - 1);
    int bh = b * NHEADS + h;

    const __half* row = qkv + (size_t)m * 3072 + h * 64;
    float q1 = __half2float(row[lane]),        q2 = __half2float(row[lane + 32]);
    float k1 = __half2float(row[1024 + lane]), k2 = __half2float(row[1024 + lane + 32]);
    float v1 = __half2float(row[2048 + lane]), v2 = __half2float(row[2048 + lane + 32]);

    float qs = q1 * q1 + q2 * q2, ks = k1 * k1 + k2 * k2;
    #pragma unroll
    for (int o = 16; o > 0; o >>= 1) {
        qs += __shfl_xor_sync(0xffffffffu, qs, o);
        ks += __shfl_xor_sync(0xffffffffu, ks, o);
    }
    float qinv = 8.0f / fmaxf(sqrtf(qs), 1e-12f);
    float kinv = 1.0f / fmaxf(sqrtf(ks), 1e-12f);
    q1 = q1 * qinv * q_scale[lane];  q2 = q2 * qinv * q_scale[lane + 32];
    k1 = k1 * kinv * k_scale[lane];  k2 = k2 * kinv * k_scale[lane + 32];

    int tq = nn + 128, tk = nn;
    float cq = g_cos[tq * 32 + lane], sq = g_sin[tq * 32 + lane];
    float ck = g_cos[tk * 32 + lane], sk = g_sin[tk * 32 + lane];
    float qo1 = q1 * cq - q2 * sq, qo2 = q2 * cq + q1 * sq;
    float ko1 = k1 * ck - k2 * sk, ko2 = k2 * ck + k1 * sk;

    size_t base = ((size_t)bh * SEQ + nn) * 64;
    g_q16[base + lane]      = __float2half(qo1);
    g_q16[base + lane + 32] = __float2half(qo2);
    g_k16[base + lane]      = __float2half(ko1);
    g_k16[base + lane + 32] = __float2half(ko2);
    g_vh[base + lane]       = __float2half(v1);
    g_vh[base + lane + 32]  = __float2half(v2);
}

// -------- windowed attention: all-fp16 HMMA flash, K/V cp.async prefetch -----
#define AQ    0u
#define AK0   18432u
#define AVR0  55296u
#define AVT   92160u
#define ATTN_SMEM 109568

__global__ void __launch_bounds__(256, 2) local_attn_kernel() {
    int w = blockIdx.x, bh = blockIdx.y;
    extern __shared__ __align__(16) unsigned char sm[];
    uint32_t smb = smem_u32g(sm);
    int tid = threadIdx.x, wid = tid >> 5, lane = tid & 31;
    int g = lane >> 2, tg = lane & 3, lr = lane & 15, lh = lane >> 4;

    size_t qoff = ((size_t)bh * SEQ + (size_t)w * 128) * 64;
    #pragma unroll
    for (int it = 0; it < 4; it++) {
        int c = tid + it * 256;
        int r = c >> 3, k16 = (c & 7) * 16;
        *(uint4*)(sm + AQ + r * 144 + k16) = *(const uint4*)((const char*)(g_q16 + qoff + (size_t)r * 64) + k16);
    }

#define PREFETCH(chunkIdx, buf) do { \
    size_t koff_ = ((size_t)bh * SEQ + (size_t)(w - 1 + (chunkIdx)) * 128) * 64; \
    const __half* kg_ = g_k16 + koff_; \
    const __half* vg_ = g_vh + koff_; \
    uint32_t kb_ = smb + AK0 + (uint32_t)(buf) * 18432u; \
    uint32_t vb_ = smb + AVR0 + (uint32_t)(buf) * 18432u; \
    _Pragma("unroll") \
    for (int it_ = 0; it_ < 4; it_++) { \
        int c_ = tid + it_ * 256; \
        int r_ = c_ >> 3, o_ = (c_ & 7) * 16; \
        asm volatile("cp.async.cg.shared.global [%0], [%1], 16;" \
            :: "r"(kb_ + r_ * 144 + o_), "l"((const char*)(kg_ + (size_t)r_ * 64) + o_)); \
        asm volatile("cp.async.cg.shared.global [%0], [%1], 16;" \
            :: "r"(vb_ + r_ * 144 + o_), "l"((const char*)(vg_ + (size_t)r_ * 64) + o_)); \
    } \
    asm volatile("cp.async.commit_group;" ::: "memory"); \
} while (0)

    float Oc[8][4];
    #pragma unroll
    for (int dt = 0; dt < 8; dt++)
        #pragma unroll
        for (int e = 0; e < 4; e++) Oc[dt][e] = 0.0f;
    float m0 = -1e30f, m1 = -1e30f, l0 = 0.0f, l1 = 0.0f;
    int r0 = wid * 16 + g, r1 = r0 + 8;
    uint32_t qrow = (uint32_t)((wid * 16 + lr) * 144 + lh * 16);

    int cfirst = (w == 0) ? 1 : 0;
    int clast  = (w == NWIN - 1) ? 1 : 2;
    int buf = 0;
    PREFETCH(cfirst, 0);

    for (int ch = cfirst; ch <= clast; ch++) {
        asm volatile("cp.async.wait_group 0;" ::: "memory");
        __syncthreads();   // chunk data ready; prior compute done (AVT free)

        // transpose V raw [j][d] -> AVT [d][j] (half2 j-pairs)
        {
            unsigned char* vr = sm + AVR0 + buf * 18432;
            #pragma unroll
            for (int it = 0; it < 4; it++) {
                int t = tid + it * 256;
                int d4 = t & 15, j2 = t >> 4;
                uint2 ua = *(const uint2*)(vr + (2 * j2) * 144 + d4 * 8);
                uint2 ub = *(const uint2*)(vr + (2 * j2 + 1) * 144 + d4 * 8);
                int d = d4 * 4;
                *(uint32_t*)(sm + AVT + (d + 0) * 272 + j2 * 4) = __byte_perm(ua.x, ub.x, 0x5410);
                *(uint32_t*)(sm + AVT + (d + 1) * 272 + j2 * 4) = __byte_perm(ua.x, ub.x, 0x7632);
                *(uint32_t*)(sm + AVT + (d + 2) * 272 + j2 * 4) = __byte_perm(ua.y, ub.y, 0x5410);
                *(uint32_t*)(sm + AVT + (d + 3) * 272 + j2 * 4) = __byte_perm(ua.y, ub.y, 0x7632);
            }
        }
        __syncthreads();

        if (ch < clast) PREFETCH(ch + 1, buf ^ 1);

        uint32_t akb = AK0 + (uint32_t)buf * 18432u;

        float Sc[16][4];
        #pragma unroll
        for (int nt = 0; nt < 16; nt++)
            #pragma unroll
            for (int e = 0; e < 4; e++) Sc[nt][e] = 0.0f;

        #pragma unroll
        for (int kd = 0; kd < 4; kd++) {
            uint32_t ah[4];
            LDMX4(ah[0], ah[1], ah[2], ah[3], smb + AQ + qrow + kd * 32);
            #pragma unroll
            for (int bp = 0; bp < 8; bp++) {
                uint32_t krow = akb + (uint32_t)((bp * 16 + lr) * 144 + kd * 32 + lh * 16);
                uint32_t t0, t1, t2, t3;
                LDMX4(t0, t1, t2, t3, smb + krow);
                hmma16816h(Sc[2*bp],   ah[0], ah[1], ah[2], ah[3], t0, t2);
                hmma16816h(Sc[2*bp+1], ah[0], ah[1], ah[2], ah[3], t1, t3);
            }
        }

        if (ch == 0) {
            #pragma unroll
            for (int nt = 0; nt < 16; nt++) {
                int c0 = nt * 8 + tg * 2;
                if (c0 < r0)     Sc[nt][0] = -1e30f;
                if (c0 + 1 < r0) Sc[nt][1] = -1e30f;
                if (c0 < r1)     Sc[nt][2] = -1e30f;
                if (c0 + 1 < r1) Sc[nt][3] = -1e30f;
            }
        } else if (ch == 2) {
            #pragma unroll
            for (int nt = 0; nt < 16; nt++) {
                int c0 = nt * 8 + tg * 2;
                if (c0 > r0)     Sc[nt][0] = -1e30f;
                if (c0 + 1 > r0) Sc[nt][1] = -1e30f;
                if (c0 > r1)     Sc[nt][2] = -1e30f;
                if (c0 + 1 > r1) Sc[nt][3] = -1e30f;
            }
        }

        float rm0 = -1e30f, rm1 = -1e30f;
        #pragma unroll
        for (int nt = 0; nt < 16; nt++) {
            rm0 = fmaxf(rm0, fmaxf(Sc[nt][0], Sc[nt][1]));
            rm1 = fmaxf(rm1, fmaxf(Sc[nt][2], Sc[nt][3]));
        }
        rm0 = fmaxf(rm0, __shfl_xor_sync(0xffffffffu, rm0, 1));
        rm0 = fmaxf(rm0, __shfl_xor_sync(0xffffffffu, rm0, 2));
        rm1 = fmaxf(rm1, __shfl_xor_sync(0xffffffffu, rm1, 1));
        rm1 = fmaxf(rm1, __shfl_xor_sync(0xffffffffu, rm1, 2));
        float mn0 = fmaxf(m0, rm0), mn1 = fmaxf(m1, rm1);
        float a0 = fexp(m0 - mn0), a1 = fexp(m1 - mn1);
        float rs0 = 0.0f, rs1 = 0.0f;
        #pragma unroll
        for (int nt = 0; nt < 16; nt++) {
            Sc[nt][0] = fexp(Sc[nt][0] - mn0);
            Sc[nt][1] = fexp(Sc[nt][1] - mn0);
            Sc[nt][2] = fexp(Sc[nt][2] - mn1);
            Sc[nt][3] = fexp(Sc[nt][3] - mn1);
            rs0 += Sc[nt][0] + Sc[nt][1];
            rs1 += Sc[nt][2] + Sc[nt][3];
        }
        rs0 += __shfl_xor_sync(0xffffffffu, rs0, 1);
        rs0 += __shfl_xor_sync(0xffffffffu, rs0, 2);
        rs1 += __shfl_xor_sync(0xffffffffu, rs1, 1);
        rs1 += __shfl_xor_sync(0xffffffffu, rs1, 2);
        l0 = l0 * a0 + rs0; l1 = l1 * a1 + rs1;
        m0 = mn0; m1 = mn1;
        #pragma unroll
        for (int dt = 0; dt < 8; dt++) {
            Oc[dt][0] *= a0; Oc[dt][1] *= a0;
            Oc[dt][2] *= a1; Oc[dt][3] *= a1;
        }

        #pragma unroll
        for (int jt = 0; jt < 8; jt++) {
            uint32_t ph[4];
            float* s0 = Sc[2*jt];
            float* s1 = Sc[2*jt+1];
            ph[0] = pack_h(s0[0], s0[1]); ph[1] = pack_h(s0[2], s0[3]);
            ph[2] = pack_h(s1[0], s1[1]); ph[3] = pack_h(s1[2], s1[3]);
            #pragma unroll
            for (int dt = 0; dt < 4; dt++) {
                uint32_t vrow = AVT + (uint32_t)((dt * 16 + lr) * 272 + jt * 32 + lh * 16);
                uint32_t t0, t1, t2, t3;
                LDMX4(t0, t1, t2, t3, smb + vrow);
                hmma16816h(Oc[2*dt],   ph[0], ph[1], ph[2], ph[3], t0, t2);
                hmma16816h(Oc[2*dt+1], ph[0], ph[1], ph[2], ph[3], t1, t3);
            }
        }
        buf ^= 1;
    }

    float i0 = 1.0f / l0, i1 = 1.0f / l1;
    int b = bh >> 4, h = bh & 15;
    size_t mr0 = (size_t)(b * SEQ + w * 128 + r0) * KDIM;
    size_t mr1 = (size_t)(b * SEQ + w * 128 + r1) * KDIM;
    #pragma unroll
    for (int dt = 0; dt < 8; dt++) {
        int k = h * 64 + dt * 8 + tg * 2;
        *(__half2*)(g_a + mr0 + k) = __floats2half2_rn(Oc[dt][0] * i0, Oc[dt][1] * i0);
        *(__half2*)(g_a + mr1 + k) = __floats2half2_rn(Oc[dt][2] * i1, Oc[dt][3] * i1);
    }
#undef PREFETCH
}

// ---------------- launch ----------------
extern "C" void kernel_launch(void* const* d_in, const int* in_sizes, int n_in,
                              void* d_out, int out_size) {
    const float* x       = (const float*)d_in[0];
    const float* w_qkv   = (const float*)d_in[1];
    const float* w_out   = (const float*)d_in[2];
    const float* q_scale = (const float*)d_in[3];
    const float* k_scale = (const float*)d_in[4];
    float* out = (float*)d_out;

    void *p_qkv16, *p_a, *p_b1, *p_b2;
    cudaGetSymbolAddress(&p_qkv16, g_qkv16);
    cudaGetSymbolAddress(&p_a, g_a);
    cudaGetSymbolAddress(&p_b1, g_b1);
    cudaGetSymbolAddress(&p_b2, g_b2);

    cudaFuncSetAttribute(local_attn_kernel,
                         cudaFuncAttributeMaxDynamicSharedMemorySize, ATTN_SMEM);
    cudaFuncSetAttribute(gemmh_kernel,
                         cudaFuncAttributeMaxDynamicSharedMemorySize, GEMM_SMEM);

    // gemm1 kept in the ncu-profiled slot (4th launch)
    rope_table_kernel<<<(TBLROWS * 32 + 255) / 256, 256>>>();
    convert_a_h<<<(NTOK * KDIM) / 1024, 256>>>(x, (__half*)p_a);
    convert_b_h<<<dim3(3072 / 32, 1024 / 32), dim3(32, 32)>>>(
        w_qkv, (__half*)p_b1, 3072);

    gemmh_kernel<<<dim3(3072 / 128, NTOK / 256), 512, GEMM_SMEM>>>(
        (const __half*)p_a, (const __half*)p_b1, (float*)p_qkv16, 3072, 1);

    convert_b_h<<<dim3(1024 / 32, 1024 / 32), dim3(32, 32)>>>(
        w_out, (__half*)p_b2, 1024);

    norm_rope_split_kernel<<<(NTOK * NHEADS) / 8, dim3(32, 8)>>>(
        (const __half*)p_qkv16, q_scale, k_scale);

    local_attn_kernel<<<dim3(NWIN, BHTOT), 256, ATTN_SMEM>>>();

    gemmh_kernel<<<dim3(1024 / 128, NTOK / 256), 512, GEMM_SMEM>>>(
        (const __half*)p_a, (const __half*)p_b2, out, 1024, 0);
}